// round 9
// baseline (speedup 1.0000x reference)
#include <cuda_runtime.h>
#include <cuda_bf16.h>
#include <float.h>
#include <cstdint>

#define NROWS 16384
#define DIM   2048
#define DSTR  2049
#define KC    1000
#define NPAD  1024
#define NSTEPS 192           // 3 segments * (2048/32)
#define STAGE_BYTES 20480    // A tile 10240 + B tile 10240 (128 rows * 80B)
#define NSTAGE 3
#define SM_TOTAL (NSTAGE * STAGE_BYTES)

// ---------------- scratch ----------------
__device__ unsigned long long g_best[NROWS];
__device__ float g_inv[NROWS];
__device__ float g_halfc[NPAD];
__device__ float g_clast[NPAD];
__device__ __nv_bfloat16 g_ahi[(size_t)NROWS * DIM];
__device__ __nv_bfloat16 g_alo[(size_t)NROWS * DIM];
__device__ __nv_bfloat16 g_chi[(size_t)NPAD * DIM];
__device__ __nv_bfloat16 g_clo[(size_t)NPAD * DIM];

__device__ __forceinline__ uint32_t smem_u32(const void* p) {
    uint32_t a;
    asm("{ .reg .u64 t; cvta.to.shared.u64 t, %1; cvt.u32.u64 %0, t; }" : "=r"(a) : "l"(p));
    return a;
}
__device__ __forceinline__ void cp16(uint32_t saddr, const void* gptr) {
    asm volatile("cp.async.cg.shared.global [%0], [%1], 16;"
                 :: "r"(saddr), "l"(__cvta_generic_to_global(gptr)));
}
#define CP_COMMIT() asm volatile("cp.async.commit_group;" ::: "memory")
#define CP_WAIT(n)  asm volatile("cp.async.wait_group %0;" :: "n"(n) : "memory")

__device__ __forceinline__ void ldmx4(uint32_t* r, uint32_t addr) {
    asm volatile("ldmatrix.sync.aligned.m8n8.x4.shared.b16 {%0,%1,%2,%3}, [%4];"
                 : "=r"(r[0]), "=r"(r[1]), "=r"(r[2]), "=r"(r[3]) : "r"(addr));
}
__device__ __forceinline__ void mma16816(float* d, const uint32_t* a, const uint32_t* b) {
    asm volatile(
        "mma.sync.aligned.m16n8k16.row.col.f32.bf16.bf16.f32 "
        "{%0,%1,%2,%3}, {%4,%5,%6,%7}, {%8,%9}, {%0,%1,%2,%3};"
        : "+f"(d[0]), "+f"(d[1]), "+f"(d[2]), "+f"(d[3])
        : "r"(a[0]), "r"(a[1]), "r"(a[2]), "r"(a[3]), "r"(b[0]), "r"(b[1]));
}

// ---------------- prep ----------------
__global__ void k_init_best() {
    int i = blockIdx.x * blockDim.x + threadIdx.x;
    if (i < NROWS) g_best[i] = 0ull;
}

// FUSED: one block per feature row. bf16 hi/lo split + fp64 row norm in one pass.
__global__ __launch_bounds__(256) void k_convert_rowinv(const float* __restrict__ A) {
    const int row = blockIdx.x;
    const int tid = threadIdx.x;
    const float4* p = (const float4*)(A + (size_t)row * DIM);
    double sum = 0.0;
    #pragma unroll
    for (int i = 0; i < 2; ++i) {
        int idx = tid + i * 256;            // float4 index 0..511
        float4 v = p[idx];
        float f[4] = {v.x, v.y, v.z, v.w};
        sum += (double)v.x * v.x + (double)v.y * v.y
             + (double)v.z * v.z + (double)v.w * v.w;
        __nv_bfloat16 h[4], l[4];
        #pragma unroll
        for (int j = 0; j < 4; j++) {
            h[j] = __float2bfloat16(f[j]);
            l[j] = __float2bfloat16(f[j] - __bfloat162float(h[j]));
        }
        size_t o = (size_t)row * 512 + idx;  // ushort4 index
        ((ushort4*)g_ahi)[o] = make_ushort4(__bfloat16_as_ushort(h[0]), __bfloat16_as_ushort(h[1]),
                                            __bfloat16_as_ushort(h[2]), __bfloat16_as_ushort(h[3]));
        ((ushort4*)g_alo)[o] = make_ushort4(__bfloat16_as_ushort(l[0]), __bfloat16_as_ushort(l[1]),
                                            __bfloat16_as_ushort(l[2]), __bfloat16_as_ushort(l[3]));
    }
    __shared__ double red[8];
    #pragma unroll
    for (int o = 16; o > 0; o >>= 1) sum += __shfl_xor_sync(0xffffffffu, sum, o);
    if ((tid & 31) == 0) red[tid >> 5] = sum;
    __syncthreads();
    if (tid == 0) {
        double s = 0.0;
        #pragma unroll
        for (int w = 0; w < 8; w++) s += red[w];
        g_inv[row] = (float)(1.0 / sqrt(s + 1.0));
    }
}

__global__ void k_prep_centers(const float* __restrict__ C) {
    int k = blockIdx.x;          // 0..1023
    int tid = threadIdx.x;       // 256
    if (k >= KC) {
        for (int i = tid; i < DIM; i += 256) {
            g_chi[(size_t)k * DIM + i] = __float2bfloat16(0.f);
            g_clo[(size_t)k * DIM + i] = __float2bfloat16(0.f);
        }
        if (tid == 0) { g_halfc[k] = 1e30f; g_clast[k] = 0.f; }  // pad: never wins
        return;
    }
    const float* row = C + (size_t)k * DSTR;
    double sum = 0.0;
    for (int i = tid; i < DSTR; i += 256) {
        float v = row[i];
        sum += (double)v * (double)v;
        if (i < DIM) {
            __nv_bfloat16 h = __float2bfloat16(v);
            g_chi[(size_t)k * DIM + i] = h;
            g_clo[(size_t)k * DIM + i] = __float2bfloat16(v - __bfloat162float(h));
        }
    }
    __shared__ double red[8];
    #pragma unroll
    for (int o = 16; o > 0; o >>= 1) sum += __shfl_xor_sync(0xffffffffu, sum, o);
    if ((tid & 31) == 0) red[tid >> 5] = sum;
    __syncthreads();
    if (tid == 0) {
        double s = 0.0;
        #pragma unroll
        for (int w = 0; w < 8; w++) s += red[w];
        g_halfc[k] = (float)(0.5 * s);
        g_clast[k] = row[DIM];
    }
}

// ---------------- HMMA bf16-split GEMM + fused argmax (unchanged from R8) ----------------
__global__ __launch_bounds__(256) void k_gemm_mma() {
    extern __shared__ char smem[];
    const uint32_t sb = smem_u32(smem);
    const int tid = threadIdx.x;
    const int wid = tid >> 5, lane = tid & 31;
    const int gid = lane >> 2, tig = lane & 3;
    const int n0 = blockIdx.x * 128;
    const int m0 = blockIdx.y * 128;
    const int wm = wid >> 1;       // 0..3, 32 m-rows
    const int wn = wid & 1;        // 0..1, 64 n-cols

    float acc[2][8][4];
    #pragma unroll
    for (int a = 0; a < 2; a++)
        #pragma unroll
        for (int b = 0; b < 8; b++)
            #pragma unroll
            for (int c = 0; c < 4; c++) acc[a][b][c] = 0.f;

    const int rc = tid >> 2;              // 0..63
    const int cc = tid & 3;               // 16B chunk in 64B row slab

    const uint32_t aoff = (uint32_t)((wm * 32 + (lane & 15)) * 80 + (lane >> 4) * 16);
    const uint32_t boff = (uint32_t)((wn * 64 + (lane & 7) + ((lane >> 4) << 3)) * 80
                                     + ((lane >> 3) & 1) * 16);

    #define LOAD_STAGE(s, st) do {                                              \
        int seg_ = (s) >> 6;                                                    \
        int k0_  = ((s) & 63) << 5;                                             \
        const __nv_bfloat16* Ag_ = (seg_ == 2) ? g_alo : g_ahi;                 \
        const __nv_bfloat16* Bg_ = (seg_ == 1) ? g_clo : g_chi;                 \
        uint32_t sa_ = sb + (st) * STAGE_BYTES;                                 \
        uint32_t sbb_ = sa_ + 10240;                                            \
        cp16(sa_  + rc * 80 + cc * 16,        Ag_ + (size_t)(m0 + rc) * DIM + k0_ + cc * 8); \
        cp16(sa_  + (rc + 64) * 80 + cc * 16, Ag_ + (size_t)(m0 + rc + 64) * DIM + k0_ + cc * 8); \
        cp16(sbb_ + rc * 80 + cc * 16,        Bg_ + (size_t)(n0 + rc) * DIM + k0_ + cc * 8); \
        cp16(sbb_ + (rc + 64) * 80 + cc * 16, Bg_ + (size_t)(n0 + rc + 64) * DIM + k0_ + cc * 8); \
    } while (0)

    LOAD_STAGE(0, 0); CP_COMMIT();
    LOAD_STAGE(1, 1); CP_COMMIT();

    for (int s = 0; s < NSTEPS; ++s) {
        CP_WAIT(1);
        __syncthreads();
        if (s + 2 < NSTEPS) LOAD_STAGE(s + 2, (s + 2) % NSTAGE);
        CP_COMMIT();

        const uint32_t stA = sb + (s % NSTAGE) * STAGE_BYTES;
        const uint32_t stB = stA + 10240;
        #pragma unroll
        for (int kk = 0; kk < 2; ++kk) {
            uint32_t af[2][4];
            ldmx4(af[0], stA + aoff + kk * 32);
            ldmx4(af[1], stA + aoff + 1280 + kk * 32);
            uint32_t bf[8][2];
            #pragma unroll
            for (int np = 0; np < 4; ++np) {
                uint32_t r[4];
                ldmx4(r, stB + boff + np * 1280 + kk * 32);
                bf[2 * np][0] = r[0]; bf[2 * np][1] = r[1];
                bf[2 * np + 1][0] = r[2]; bf[2 * np + 1][1] = r[3];
            }
            #pragma unroll
            for (int mf = 0; mf < 2; ++mf)
                #pragma unroll
                for (int nf = 0; nf < 8; ++nf)
                    mma16816(acc[mf][nf], af[mf], bf[nf]);
        }
    }

    float cl[16], hc[16];
    #pragma unroll
    for (int nf = 0; nf < 8; ++nf)
        #pragma unroll
        for (int j = 0; j < 2; ++j) {
            int n = n0 + wn * 64 + nf * 8 + 2 * tig + j;
            cl[nf * 2 + j] = g_clast[n];
            hc[nf * 2 + j] = g_halfc[n];
        }

    #pragma unroll
    for (int mf = 0; mf < 2; ++mf)
        #pragma unroll
        for (int h = 0; h < 2; ++h) {
            int m = m0 + wm * 32 + mf * 16 + gid + 8 * h;
            float invm = g_inv[m];
            float bs = -FLT_MAX;
            int bn = 0x7FFFFFFF;
            #pragma unroll
            for (int nf = 0; nf < 8; ++nf)
                #pragma unroll
                for (int j = 0; j < 2; ++j) {
                    float s = fmaf(acc[mf][nf][2 * h + j] + cl[nf * 2 + j], invm,
                                   -hc[nf * 2 + j]);
                    int n = n0 + wn * 64 + nf * 8 + 2 * tig + j;
                    if (s > bs) { bs = s; bn = n; }
                }
            #pragma unroll
            for (int o = 1; o <= 2; o <<= 1) {
                float so = __shfl_xor_sync(0xffffffffu, bs, o);
                int   no = __shfl_xor_sync(0xffffffffu, bn, o);
                if (so > bs || (so == bs && no < bn)) { bs = so; bn = no; }
            }
            if (tig == 0) {
                unsigned sbits = __float_as_uint(bs);
                sbits = (sbits & 0x80000000u) ? ~sbits : (sbits | 0x80000000u);
                unsigned long long packed = ((unsigned long long)sbits << 32)
                    | (unsigned long long)(0xFFFFFFFFu - (unsigned)bn);
                atomicMax(&g_best[m], packed);
            }
        }
}

__global__ void k_decode(float* __restrict__ out) {
    int i = blockIdx.x * blockDim.x + threadIdx.x;
    if (i < NROWS)
        out[i] = (float)(0xFFFFFFFFu - (unsigned)(g_best[i] & 0xFFFFFFFFull));
}

extern "C" void kernel_launch(void* const* d_in, const int* in_sizes, int n_in,
                              void* d_out, int out_size) {
    (void)in_sizes; (void)n_in; (void)out_size;
    const float* feats = (const float*)d_in[0];
    const float* initc = (const float*)d_in[1];
    float* out = (float*)d_out;

    cudaFuncSetAttribute(k_gemm_mma, cudaFuncAttributeMaxDynamicSharedMemorySize, SM_TOTAL);

    k_init_best<<<(NROWS + 255) / 256, 256>>>();
    k_convert_rowinv<<<NROWS, 256>>>(feats);
    k_prep_centers<<<NPAD, 256>>>(initc);

    dim3 grid(NPAD / 128, NROWS / 128);   // (8, 128)
    k_gemm_mma<<<grid, 256, SM_TOTAL>>>();

    k_decode<<<(NROWS + 255) / 256, 256>>>(out);
}

// round 10
// speedup vs baseline: 1.4104x; 1.4104x over previous
#include <cuda_runtime.h>
#include <cuda_bf16.h>
#include <float.h>
#include <cstdint>

#define NROWS 16384
#define DIM   2048
#define DSTR  2049
#define KC    1000
#define NPAD  1024
#define NSTEPS 192           // 3 segments * (2048/32)
#define STAGE_BYTES 20480    // A tile 10240 + B tile 10240 (128 rows * 80B)
#define NSTAGE 3
#define SM_TOTAL (NSTAGE * STAGE_BYTES)

// ---------------- scratch ----------------
__device__ unsigned long long g_best[NROWS];
__device__ float g_inv[NROWS];
__device__ float g_halfc[NPAD];
__device__ float g_clast[NPAD];
__device__ __nv_bfloat16 g_ahi[(size_t)NROWS * DIM];
__device__ __nv_bfloat16 g_alo[(size_t)NROWS * DIM];
__device__ __nv_bfloat16 g_chi[(size_t)NPAD * DIM];
__device__ __nv_bfloat16 g_clo[(size_t)NPAD * DIM];

__device__ __forceinline__ uint32_t smem_u32(const void* p) {
    uint32_t a;
    asm("{ .reg .u64 t; cvta.to.shared.u64 t, %1; cvt.u32.u64 %0, t; }" : "=r"(a) : "l"(p));
    return a;
}
__device__ __forceinline__ void cp16(uint32_t saddr, const void* gptr) {
    asm volatile("cp.async.cg.shared.global [%0], [%1], 16;"
                 :: "r"(saddr), "l"(__cvta_generic_to_global(gptr)));
}
#define CP_COMMIT() asm volatile("cp.async.commit_group;" ::: "memory")
#define CP_WAIT(n)  asm volatile("cp.async.wait_group %0;" :: "n"(n) : "memory")

__device__ __forceinline__ void ldmx4(uint32_t* r, uint32_t addr) {
    asm volatile("ldmatrix.sync.aligned.m8n8.x4.shared.b16 {%0,%1,%2,%3}, [%4];"
                 : "=r"(r[0]), "=r"(r[1]), "=r"(r[2]), "=r"(r[3]) : "r"(addr));
}
__device__ __forceinline__ void mma16816(float* d, const uint32_t* a, const uint32_t* b) {
    asm volatile(
        "mma.sync.aligned.m16n8k16.row.col.f32.bf16.bf16.f32 "
        "{%0,%1,%2,%3}, {%4,%5,%6,%7}, {%8,%9}, {%0,%1,%2,%3};"
        : "+f"(d[0]), "+f"(d[1]), "+f"(d[2]), "+f"(d[3])
        : "r"(a[0]), "r"(a[1]), "r"(a[2]), "r"(a[3]), "r"(b[0]), "r"(b[1]));
}

// ---------------- prep ----------------
__global__ void k_init_best() {
    int i = blockIdx.x * blockDim.x + threadIdx.x;
    if (i < NROWS) g_best[i] = 0ull;
}

// One block per feature row: bf16 hi/lo split + fp32 row norm in one pass.
// fp32 accumulation: norm rel-err ~3e-6 -> score err ~1e-6, negligible vs gaps.
__global__ __launch_bounds__(256) void k_convert_rowinv(const float* __restrict__ A) {
    const int row = blockIdx.x;
    const int tid = threadIdx.x;
    const float4* p = (const float4*)(A + (size_t)row * DIM);
    float sum = 0.f;
    #pragma unroll
    for (int i = 0; i < 2; ++i) {
        int idx = tid + i * 256;            // float4 index 0..511
        float4 v = p[idx];
        float f[4] = {v.x, v.y, v.z, v.w};
        sum = fmaf(v.x, v.x, sum); sum = fmaf(v.y, v.y, sum);
        sum = fmaf(v.z, v.z, sum); sum = fmaf(v.w, v.w, sum);
        __nv_bfloat16 h[4], l[4];
        #pragma unroll
        for (int j = 0; j < 4; j++) {
            h[j] = __float2bfloat16(f[j]);
            l[j] = __float2bfloat16(f[j] - __bfloat162float(h[j]));
        }
        size_t o = (size_t)row * 512 + idx;  // ushort4 index
        ((ushort4*)g_ahi)[o] = make_ushort4(__bfloat16_as_ushort(h[0]), __bfloat16_as_ushort(h[1]),
                                            __bfloat16_as_ushort(h[2]), __bfloat16_as_ushort(h[3]));
        ((ushort4*)g_alo)[o] = make_ushort4(__bfloat16_as_ushort(l[0]), __bfloat16_as_ushort(l[1]),
                                            __bfloat16_as_ushort(l[2]), __bfloat16_as_ushort(l[3]));
    }
    __shared__ float red[8];
    #pragma unroll
    for (int o = 16; o > 0; o >>= 1) sum += __shfl_xor_sync(0xffffffffu, sum, o);
    if ((tid & 31) == 0) red[tid >> 5] = sum;
    __syncthreads();
    if (tid == 0) {
        float s = 0.f;
        #pragma unroll
        for (int w = 0; w < 8; w++) s += red[w];
        g_inv[row] = (float)(1.0 / sqrt((double)s + 1.0));
    }
}

__global__ void k_prep_centers(const float* __restrict__ C) {
    int k = blockIdx.x;          // 0..1023
    int tid = threadIdx.x;       // 256
    if (k >= KC) {
        for (int i = tid; i < DIM; i += 256) {
            g_chi[(size_t)k * DIM + i] = __float2bfloat16(0.f);
            g_clo[(size_t)k * DIM + i] = __float2bfloat16(0.f);
        }
        if (tid == 0) { g_halfc[k] = 1e30f; g_clast[k] = 0.f; }  // pad: never wins
        return;
    }
    const float* row = C + (size_t)k * DSTR;
    double sum = 0.0;
    for (int i = tid; i < DSTR; i += 256) {
        float v = row[i];
        sum += (double)v * (double)v;
        if (i < DIM) {
            __nv_bfloat16 h = __float2bfloat16(v);
            g_chi[(size_t)k * DIM + i] = h;
            g_clo[(size_t)k * DIM + i] = __float2bfloat16(v - __bfloat162float(h));
        }
    }
    __shared__ double red[8];
    #pragma unroll
    for (int o = 16; o > 0; o >>= 1) sum += __shfl_xor_sync(0xffffffffu, sum, o);
    if ((tid & 31) == 0) red[tid >> 5] = sum;
    __syncthreads();
    if (tid == 0) {
        double s = 0.0;
        #pragma unroll
        for (int w = 0; w < 8; w++) s += red[w];
        g_halfc[k] = (float)(0.5 * s);
        g_clast[k] = row[DIM];
    }
}

// ---------------- HMMA bf16-split GEMM + fused argmax ----------------
// 128 threads, 4 warps in 2x2; warp tile 64x64 -> 8 LDSM : 32 MMA per kk.
__global__ __launch_bounds__(128) void k_gemm_mma() {
    extern __shared__ char smem[];
    const uint32_t sb = smem_u32(smem);
    const int tid = threadIdx.x;
    const int wid = tid >> 5, lane = tid & 31;
    const int gid = lane >> 2, tig = lane & 3;
    const int n0 = blockIdx.x * 128;
    const int m0 = blockIdx.y * 128;
    const int wm = wid >> 1;       // 0..1, 64 m-rows
    const int wn = wid & 1;        // 0..1, 64 n-cols

    float acc[4][8][4];
    #pragma unroll
    for (int a = 0; a < 4; a++)
        #pragma unroll
        for (int b = 0; b < 8; b++)
            #pragma unroll
            for (int c = 0; c < 4; c++) acc[a][b][c] = 0.f;

    // loader: 128 threads, 8 cp16 each (A 4 rows + B 4 rows)
    const int rc = tid >> 2;              // 0..31
    const int cc = tid & 3;               // 16B chunk in 64B row slab

    const uint32_t aoff = (uint32_t)((wm * 64 + (lane & 15)) * 80 + (lane >> 4) * 16);
    const uint32_t boff = (uint32_t)((wn * 64 + (lane & 7) + ((lane >> 4) << 3)) * 80
                                     + ((lane >> 3) & 1) * 16);

    #define LOAD_STAGE(s, st) do {                                              \
        int seg_ = (s) >> 6;                                                    \
        int k0_  = ((s) & 63) << 5;                                             \
        const __nv_bfloat16* Ag_ = (seg_ == 2) ? g_alo : g_ahi;                 \
        const __nv_bfloat16* Bg_ = (seg_ == 1) ? g_clo : g_chi;                 \
        uint32_t sa_ = sb + (st) * STAGE_BYTES;                                 \
        uint32_t sbb_ = sa_ + 10240;                                            \
        _Pragma("unroll")                                                       \
        for (int rb_ = 0; rb_ < 4; rb_++) {                                     \
            int r_ = rc + rb_ * 32;                                             \
            cp16(sa_  + r_ * 80 + cc * 16, Ag_ + (size_t)(m0 + r_) * DIM + k0_ + cc * 8); \
            cp16(sbb_ + r_ * 80 + cc * 16, Bg_ + (size_t)(n0 + r_) * DIM + k0_ + cc * 8); \
        }                                                                       \
    } while (0)

    LOAD_STAGE(0, 0); CP_COMMIT();
    LOAD_STAGE(1, 1); CP_COMMIT();

    for (int s = 0; s < NSTEPS; ++s) {
        CP_WAIT(1);
        __syncthreads();
        if (s + 2 < NSTEPS) LOAD_STAGE(s + 2, (s + 2) % NSTAGE);
        CP_COMMIT();

        const uint32_t stA = sb + (s % NSTAGE) * STAGE_BYTES;
        const uint32_t stB = stA + 10240;
        #pragma unroll
        for (int kk = 0; kk < 2; ++kk) {
            uint32_t af[4][4];
            #pragma unroll
            for (int mf = 0; mf < 4; ++mf)
                ldmx4(af[mf], stA + aoff + mf * 1280 + kk * 32);
            uint32_t bf[8][2];
            #pragma unroll
            for (int np = 0; np < 4; ++np) {
                uint32_t r[4];
                ldmx4(r, stB + boff + np * 1280 + kk * 32);
                bf[2 * np][0] = r[0]; bf[2 * np][1] = r[1];
                bf[2 * np + 1][0] = r[2]; bf[2 * np + 1][1] = r[3];
            }
            #pragma unroll
            for (int mf = 0; mf < 4; ++mf)
                #pragma unroll
                for (int nf = 0; nf < 8; ++nf)
                    mma16816(acc[mf][nf], af[mf], bf[nf]);
        }
    }

    // -------- fused epilogue --------
    float cl[16], hc[16];
    #pragma unroll
    for (int nf = 0; nf < 8; ++nf)
        #pragma unroll
        for (int j = 0; j < 2; ++j) {
            int n = n0 + wn * 64 + nf * 8 + 2 * tig + j;
            cl[nf * 2 + j] = g_clast[n];
            hc[nf * 2 + j] = g_halfc[n];
        }

    #pragma unroll
    for (int mf = 0; mf < 4; ++mf)
        #pragma unroll
        for (int h = 0; h < 2; ++h) {
            int m = m0 + wm * 64 + mf * 16 + gid + 8 * h;
            float invm = g_inv[m];
            float bs = -FLT_MAX;
            int bn = 0x7FFFFFFF;
            #pragma unroll
            for (int nf = 0; nf < 8; ++nf)
                #pragma unroll
                for (int j = 0; j < 2; ++j) {
                    float s = fmaf(acc[mf][nf][2 * h + j] + cl[nf * 2 + j], invm,
                                   -hc[nf * 2 + j]);
                    int n = n0 + wn * 64 + nf * 8 + 2 * tig + j;
                    if (s > bs) { bs = s; bn = n; }
                }
            #pragma unroll
            for (int o = 1; o <= 2; o <<= 1) {
                float so = __shfl_xor_sync(0xffffffffu, bs, o);
                int   no = __shfl_xor_sync(0xffffffffu, bn, o);
                if (so > bs || (so == bs && no < bn)) { bs = so; bn = no; }
            }
            if (tig == 0) {
                unsigned sbits = __float_as_uint(bs);
                sbits = (sbits & 0x80000000u) ? ~sbits : (sbits | 0x80000000u);
                unsigned long long packed = ((unsigned long long)sbits << 32)
                    | (unsigned long long)(0xFFFFFFFFu - (unsigned)bn);
                atomicMax(&g_best[m], packed);
            }
        }
}

__global__ void k_decode(float* __restrict__ out) {
    int i = blockIdx.x * blockDim.x + threadIdx.x;
    if (i < NROWS)
        out[i] = (float)(0xFFFFFFFFu - (unsigned)(g_best[i] & 0xFFFFFFFFull));
}

extern "C" void kernel_launch(void* const* d_in, const int* in_sizes, int n_in,
                              void* d_out, int out_size) {
    (void)in_sizes; (void)n_in; (void)out_size;
    const float* feats = (const float*)d_in[0];
    const float* initc = (const float*)d_in[1];
    float* out = (float*)d_out;

    cudaFuncSetAttribute(k_gemm_mma, cudaFuncAttributeMaxDynamicSharedMemorySize, SM_TOTAL);

    k_init_best<<<(NROWS + 255) / 256, 256>>>();
    k_convert_rowinv<<<NROWS, 256>>>(feats);
    k_prep_centers<<<NPAD, 256>>>(initc);

    dim3 grid(NPAD / 128, NROWS / 128);   // (8, 128) = 1024 CTAs
    k_gemm_mma<<<grid, 128, SM_TOTAL>>>();

    k_decode<<<(NROWS + 255) / 256, 256>>>(out);
}